// round 1
// baseline (speedup 1.0000x reference)
#include <cuda_runtime.h>
#include <cstdint>

#define NN 16384
#define EE 524288
#define BB 32
#define DD 64
#define MM 5

// ---------------- device scratch (static, allocation-free) ----------------
__device__ float g_T1[(size_t)BB * NN * DD];
__device__ float g_T2[(size_t)BB * NN * DD];
__device__ float g_T3[(size_t)BB * NN * DD];
__device__ float g_T4[(size_t)BB * NN * DD];

__device__ float g_degr[NN];
__device__ float g_degc[NN];
__device__ int   g_cnt1[NN], g_cnt2[NN];
__device__ int   g_ptr1[NN + 1], g_ptr2[NN + 1];
__device__ int   g_cur1[NN], g_cur2[NN];
__device__ int   g_src1[EE], g_src2[EE];
__device__ float g_val1[EE], g_val2[EE];

// ---------------- init ----------------
__global__ void k_zero() {
    int i = blockIdx.x * blockDim.x + threadIdx.x;
    if (i < NN) {
        g_degr[i] = 0.f; g_degc[i] = 0.f;
        g_cnt1[i] = 0;   g_cnt2[i] = 0;
    }
}

// degree sums + in-degree histograms for both CSRs
__global__ void k_degree(const int* __restrict__ rows, const int* __restrict__ cols,
                         const float* __restrict__ adj) {
    int e = blockIdx.x * blockDim.x + threadIdx.x;
    if (e >= EE) return;
    int r = rows[e], c = cols[e];
    float a = adj[e];
    atomicAdd(&g_degr[r], a);
    atomicAdd(&g_degc[c], a);
    atomicAdd(&g_cnt1[c], 1);   // S1 scatters to cols
    atomicAdd(&g_cnt2[r], 1);   // S2 scatters to rows
}

// single-block exclusive scan over 16384 counts (1024 threads x 16)
__device__ void scan16k(const int* __restrict__ cnt, int* __restrict__ ptr,
                        int* __restrict__ cur, int* sh) {
    int t = threadIdx.x;
    int base = t * 16;
    int loc[16];
    int s = 0;
#pragma unroll
    for (int j = 0; j < 16; ++j) { loc[j] = s; s += cnt[base + j]; }
    sh[t] = s;
    __syncthreads();
    for (int off = 1; off < 1024; off <<= 1) {
        int v = (t >= off) ? sh[t - off] : 0;
        __syncthreads();
        sh[t] += v;
        __syncthreads();
    }
    int pre = (t == 0) ? 0 : sh[t - 1];
#pragma unroll
    for (int j = 0; j < 16; ++j) {
        int p = pre + loc[j];
        ptr[base + j] = p;
        cur[base + j] = p;
    }
    if (t == 0) ptr[NN] = EE;
    __syncthreads();
}

__global__ void k_scan() {
    __shared__ int sh[1024];
    scan16k(g_cnt1, g_ptr1, g_cur1, sh);
    scan16k(g_cnt2, g_ptr2, g_cur2, sh);
    int t = threadIdx.x;
    for (int i = t; i < NN; i += 1024) {
        float d = g_degr[i]; g_degr[i] = (d > 0.f) ? 1.f / d : 0.f;
        d = g_degc[i];       g_degc[i] = (d > 0.f) ? 1.f / d : 0.f;
    }
}

// scatter edges into dst-sorted CSR, with normalized values baked in
__global__ void k_fill(const int* __restrict__ rows, const int* __restrict__ cols,
                       const float* __restrict__ adj) {
    int e = blockIdx.x * blockDim.x + threadIdx.x;
    if (e >= EE) return;
    int r = rows[e], c = cols[e];
    float a = adj[e];
    // S1: y[c] += a*inv_drow[r] * x[r]
    int p = atomicAdd(&g_cur1[c], 1);
    g_src1[p] = r;
    g_val1[p] = a * g_degr[r];
    // S2: y[r] += a*inv_dcol[c] * x[c]
    int q = atomicAdd(&g_cur2[r], 1);
    g_src2[q] = c;
    g_val2[q] = a * g_degc[c];
}

// ---------------- SpMM: one warp per dst node, per batch element ----------------
// X, XM, T layout: buf[(b*NN + n)*64 + d]  (rows are 256B, contiguous, aligned)
template <bool CHEB>
__global__ void __launch_bounds__(256) k_spmm(
    const int* __restrict__ ptr, const int* __restrict__ srcs,
    const float* __restrict__ vals, const float* __restrict__ X,
    const float* __restrict__ XM, float* __restrict__ T)
{
    int lane = threadIdx.x & 31;
    int n = blockIdx.x * 8 + (threadIdx.x >> 5);
    size_t boff = (size_t)blockIdx.y * (NN * DD);
    const float2* __restrict__ Xb = (const float2*)(X + boff);
    int p0 = ptr[n], p1 = ptr[n + 1];
    float ax = 0.f, ay = 0.f;
    int e = p0;
    // MLP=4: four independent row-gathers in flight per warp
    for (; e + 4 <= p1; e += 4) {
        int s0 = srcs[e], s1 = srcs[e + 1], s2 = srcs[e + 2], s3 = srcs[e + 3];
        float v0 = vals[e], v1 = vals[e + 1], v2 = vals[e + 2], v3 = vals[e + 3];
        float2 g0 = Xb[s0 * 32 + lane];
        float2 g1 = Xb[s1 * 32 + lane];
        float2 g2 = Xb[s2 * 32 + lane];
        float2 g3 = Xb[s3 * 32 + lane];
        ax = fmaf(v0, g0.x, ax); ay = fmaf(v0, g0.y, ay);
        ax = fmaf(v1, g1.x, ax); ay = fmaf(v1, g1.y, ay);
        ax = fmaf(v2, g2.x, ax); ay = fmaf(v2, g2.y, ay);
        ax = fmaf(v3, g3.x, ax); ay = fmaf(v3, g3.y, ay);
    }
    for (; e < p1; ++e) {
        int s = srcs[e]; float v = vals[e];
        float2 g = Xb[s * 32 + lane];
        ax = fmaf(v, g.x, ax); ay = fmaf(v, g.y, ay);
    }
    size_t ro = boff + (size_t)n * DD + lane * 2;
    if (CHEB) {
        float2 mv = *(const float2*)(XM + ro);
        ax = 2.f * ax - mv.x;
        ay = 2.f * ay - mv.y;
    }
    *(float2*)(T + ro) = make_float2(ax, ay);
}

// ---------------- fused projection: out[r,:] = bias + sum_m A_m[r,:] @ W_m ----------------
// 64 rows x 64 cols per block, 64 threads, 8x8 register tile, fma.rn.f32x2
__global__ void __launch_bounds__(64) k_gemm(
    const float* __restrict__ X0, const float* __restrict__ W,
    const float* __restrict__ bias, float* __restrict__ out)
{
    __shared__ float Ash[64][65];   // pad 65: a-broadcast loads hit banks {k, k+8, k+16, k+24}
    __shared__ float Wsh[64][64];
    int tid = threadIdx.x;
    int rg = tid >> 3;   // 0..7 row group
    int cg = tid & 7;    // 0..7 col group
    size_t row0 = (size_t)blockIdx.x * 64;

    unsigned long long acc[8][4];
#pragma unroll
    for (int i = 0; i < 8; ++i)
#pragma unroll
        for (int j = 0; j < 4; ++j) acc[i][j] = 0ull;

#pragma unroll
    for (int m = 0; m < 5; ++m) {
        const float* __restrict__ A =
            (m == 0) ? X0 : (m == 1) ? g_T1 : (m == 2) ? g_T2 : (m == 3) ? g_T3 : g_T4;
        // A tile [64 rows x 64]: 2 contiguous rows per warp-iteration, coalesced
#pragma unroll
        for (int idx = tid; idx < 1024; idx += 64) {
            int r = idx >> 4, c4 = idx & 15;
            float4 v = *(const float4*)(A + (row0 + r) * DD + c4 * 4);
            Ash[r][c4 * 4 + 0] = v.x; Ash[r][c4 * 4 + 1] = v.y;
            Ash[r][c4 * 4 + 2] = v.z; Ash[r][c4 * 4 + 3] = v.w;
        }
        // W_m slice: row d -> weights[(d*5 + m)*64 + o]
#pragma unroll
        for (int idx = tid; idx < 1024; idx += 64) {
            int k = idx >> 4, o4 = idx & 15;
            *(float4*)(&Wsh[k][o4 * 4]) =
                *(const float4*)(W + (size_t)(k * MM + m) * 64 + o4 * 4);
        }
        __syncthreads();
#pragma unroll 4
        for (int k = 0; k < 64; ++k) {
            const ulonglong2* wp = (const ulonglong2*)(&Wsh[k][cg * 8]);
            ulonglong2 w01 = wp[0];
            ulonglong2 w23 = wp[1];
            unsigned long long w0 = w01.x, w1 = w01.y, w2 = w23.x, w3 = w23.y;
#pragma unroll
            for (int i = 0; i < 8; ++i) {
                float a = Ash[rg * 8 + i][k];
                unsigned long long ap;
                asm("mov.b64 %0, {%1, %1};" : "=l"(ap) : "f"(a));
                asm("fma.rn.f32x2 %0, %1, %2, %0;" : "+l"(acc[i][0]) : "l"(ap), "l"(w0));
                asm("fma.rn.f32x2 %0, %1, %2, %0;" : "+l"(acc[i][1]) : "l"(ap), "l"(w1));
                asm("fma.rn.f32x2 %0, %1, %2, %0;" : "+l"(acc[i][2]) : "l"(ap), "l"(w2));
                asm("fma.rn.f32x2 %0, %1, %2, %0;" : "+l"(acc[i][3]) : "l"(ap), "l"(w3));
            }
        }
        __syncthreads();
    }

    float bb[8];
#pragma unroll
    for (int j = 0; j < 8; ++j) bb[j] = bias[cg * 8 + j];
#pragma unroll
    for (int i = 0; i < 8; ++i) {
        float res[8];
#pragma unroll
        for (int j = 0; j < 4; ++j) {
            float lo, hi;
            asm("mov.b64 {%0, %1}, %2;" : "=f"(lo), "=f"(hi) : "l"(acc[i][j]));
            res[2 * j]     = lo + bb[2 * j];
            res[2 * j + 1] = hi + bb[2 * j + 1];
        }
        float* op = out + (row0 + rg * 8 + i) * DD + cg * 8;
        *(float4*)(op)     = make_float4(res[0], res[1], res[2], res[3]);
        *(float4*)(op + 4) = make_float4(res[4], res[5], res[6], res[7]);
    }
}

// ---------------- launch ----------------
extern "C" void kernel_launch(void* const* d_in, const int* in_sizes, int n_in,
                              void* d_out, int out_size)
{
    const float* inputs  = (const float*)d_in[0];   // [B, N, D]
    const float* adj     = (const float*)d_in[1];   // [E]
    const int*   rows    = (const int*)d_in[2];     // [E]
    const int*   cols    = (const int*)d_in[3];     // [E]
    const float* weights = (const float*)d_in[4];   // [D*M, OUT]
    const float* biases  = (const float*)d_in[5];   // [1, OUT]
    float* out = (float*)d_out;                     // [B, N, OUT]
    (void)in_sizes; (void)n_in; (void)out_size;

    void *pP1, *pP2, *pS1, *pS2, *pV1, *pV2, *pT1, *pT2, *pT3, *pT4;
    cudaGetSymbolAddress(&pP1, g_ptr1);
    cudaGetSymbolAddress(&pP2, g_ptr2);
    cudaGetSymbolAddress(&pS1, g_src1);
    cudaGetSymbolAddress(&pS2, g_src2);
    cudaGetSymbolAddress(&pV1, g_val1);
    cudaGetSymbolAddress(&pV2, g_val2);
    cudaGetSymbolAddress(&pT1, g_T1);
    cudaGetSymbolAddress(&pT2, g_T2);
    cudaGetSymbolAddress(&pT3, g_T3);
    cudaGetSymbolAddress(&pT4, g_T4);

    k_zero<<<(NN + 255) / 256, 256>>>();
    k_degree<<<(EE + 255) / 256, 256>>>(rows, cols, adj);
    k_scan<<<1, 1024>>>();
    k_fill<<<(EE + 255) / 256, 256>>>(rows, cols, adj);

    dim3 sg(NN / 8, BB);
    // T1 = S1 @ X0
    k_spmm<false><<<sg, 256>>>((const int*)pP1, (const int*)pS1, (const float*)pV1,
                               inputs, nullptr, (float*)pT1);
    // T2 = 2*S1 @ T1 - X0
    k_spmm<true><<<sg, 256>>>((const int*)pP1, (const int*)pS1, (const float*)pV1,
                              (const float*)pT1, inputs, (float*)pT2);
    // T3 = S2 @ T1   (x0 is NOT reset between supports, matching reference)
    k_spmm<false><<<sg, 256>>>((const int*)pP2, (const int*)pS2, (const float*)pV2,
                               (const float*)pT1, nullptr, (float*)pT3);
    // T4 = 2*S2 @ T3 - T1
    k_spmm<true><<<sg, 256>>>((const int*)pP2, (const int*)pS2, (const float*)pV2,
                              (const float*)pT3, (const float*)pT1, (float*)pT4);

    // out = [X0|T1|T2|T3|T4] (interleaved d*5+m) @ W + bias
    k_gemm<<<(BB * NN) / 64, 64>>>(inputs, weights, biases, out);
}

// round 2
// speedup vs baseline: 1.0716x; 1.0716x over previous
#include <cuda_runtime.h>
#include <cuda_fp16.h>
#include <mma.h>
#include <cstdint>

#define NN 16384
#define EE 524288
#define BB 32
#define DD 64
#define MM 5

using namespace nvcuda;

// ---------------- device scratch (static, allocation-free) ----------------
// fp16 operand buffers (gather sources + GEMM A operands)
__device__ __half g_Xh[(size_t)BB * NN * DD];   // fp16 copy of inputs
__device__ __half g_T1[(size_t)BB * NN * DD];
__device__ __half g_T2[(size_t)BB * NN * DD];
__device__ __half g_T3[(size_t)BB * NN * DD];
__device__ __half g_T4[(size_t)BB * NN * DD];
__device__ __half g_Wh[MM * DD * DD];           // W permuted: [(m*64+k)*64+o]

__device__ float g_degr[NN];
__device__ float g_degc[NN];
__device__ int   g_cnt1[NN], g_cnt2[NN];
__device__ int   g_ptr1[NN + 1], g_ptr2[NN + 1];
__device__ int   g_cur1[NN], g_cur2[NN];
__device__ int   g_src1[EE], g_src2[EE];
__device__ float g_val1[EE], g_val2[EE];

// ---------------- init ----------------
__global__ void k_zero() {
    int i = blockIdx.x * blockDim.x + threadIdx.x;
    if (i < NN) {
        g_degr[i] = 0.f; g_degc[i] = 0.f;
        g_cnt1[i] = 0;   g_cnt2[i] = 0;
    }
}

__global__ void k_degree(const int* __restrict__ rows, const int* __restrict__ cols,
                         const float* __restrict__ adj) {
    int e = blockIdx.x * blockDim.x + threadIdx.x;
    if (e >= EE) return;
    int r = rows[e], c = cols[e];
    float a = adj[e];
    atomicAdd(&g_degr[r], a);
    atomicAdd(&g_degc[c], a);
    atomicAdd(&g_cnt1[c], 1);   // S1 scatters to cols
    atomicAdd(&g_cnt2[r], 1);   // S2 scatters to rows
}

__device__ void scan16k(const int* __restrict__ cnt, int* __restrict__ ptr,
                        int* __restrict__ cur, int* sh) {
    int t = threadIdx.x;
    int base = t * 16;
    int loc[16];
    int s = 0;
#pragma unroll
    for (int j = 0; j < 16; ++j) { loc[j] = s; s += cnt[base + j]; }
    sh[t] = s;
    __syncthreads();
    for (int off = 1; off < 1024; off <<= 1) {
        int v = (t >= off) ? sh[t - off] : 0;
        __syncthreads();
        sh[t] += v;
        __syncthreads();
    }
    int pre = (t == 0) ? 0 : sh[t - 1];
#pragma unroll
    for (int j = 0; j < 16; ++j) {
        int p = pre + loc[j];
        ptr[base + j] = p;
        cur[base + j] = p;
    }
    if (t == 0) ptr[NN] = EE;
    __syncthreads();
}

__global__ void k_scan() {
    __shared__ int sh[1024];
    scan16k(g_cnt1, g_ptr1, g_cur1, sh);
    scan16k(g_cnt2, g_ptr2, g_cur2, sh);
    int t = threadIdx.x;
    for (int i = t; i < NN; i += 1024) {
        float d = g_degr[i]; g_degr[i] = (d > 0.f) ? 1.f / d : 0.f;
        d = g_degc[i];       g_degc[i] = (d > 0.f) ? 1.f / d : 0.f;
    }
}

__global__ void k_fill(const int* __restrict__ rows, const int* __restrict__ cols,
                       const float* __restrict__ adj) {
    int e = blockIdx.x * blockDim.x + threadIdx.x;
    if (e >= EE) return;
    int r = rows[e], c = cols[e];
    float a = adj[e];
    int p = atomicAdd(&g_cur1[c], 1);
    g_src1[p] = r;
    g_val1[p] = a * g_degr[r];
    int q = atomicAdd(&g_cur2[r], 1);
    g_src2[q] = c;
    g_val2[q] = a * g_degc[c];
}

// ---------------- converts ----------------
__global__ void k_cvt_x(const float* __restrict__ X) {
    size_t i = (size_t)blockIdx.x * blockDim.x + threadIdx.x;   // half2 index
    const size_t total = (size_t)BB * NN * DD / 2;
    if (i >= total) return;
    float2 v = ((const float2*)X)[i];
    ((__half2*)g_Xh)[i] = __floats2half2_rn(v.x, v.y);
}

// permute W [(k*5+m)*64+o] -> g_Wh [(m*64+k)*64+o], fp16
__global__ void k_cvt_w(const float* __restrict__ W) {
    int idx = blockIdx.x * blockDim.x + threadIdx.x;
    if (idx >= MM * DD * DD) return;
    int m = idx / (DD * DD);
    int rem = idx - m * DD * DD;
    int k = rem >> 6, o = rem & 63;
    g_Wh[idx] = __float2half(W[(size_t)(k * MM + m) * DD + o]);
}

// ---------------- SpMM (fp16 gather, fp32 accumulate) ----------------
// buffers layout: buf[(b*NN + n)*64 + d], rows are 128B fp16
template <bool CHEB>
__global__ void __launch_bounds__(256) k_spmm(
    const int* __restrict__ ptr, const int* __restrict__ srcs,
    const float* __restrict__ vals, const __half* __restrict__ X,
    const __half* __restrict__ XM, __half* __restrict__ T)
{
    int lane = threadIdx.x & 31;
    int n = blockIdx.x * 8 + (threadIdx.x >> 5);
    size_t boff2 = (size_t)blockIdx.y * (NN * 32);          // half2 units
    const __half2* __restrict__ Xb = (const __half2*)X + boff2;
    int p0 = ptr[n], p1 = ptr[n + 1];
    float ax = 0.f, ay = 0.f;
    int e = p0;
    for (; e + 4 <= p1; e += 4) {
        int s0 = srcs[e], s1 = srcs[e + 1], s2 = srcs[e + 2], s3 = srcs[e + 3];
        float v0 = vals[e], v1 = vals[e + 1], v2 = vals[e + 2], v3 = vals[e + 3];
        __half2 h0 = Xb[s0 * 32 + lane];
        __half2 h1 = Xb[s1 * 32 + lane];
        __half2 h2 = Xb[s2 * 32 + lane];
        __half2 h3 = Xb[s3 * 32 + lane];
        float2 g0 = __half22float2(h0);
        float2 g1 = __half22float2(h1);
        float2 g2 = __half22float2(h2);
        float2 g3 = __half22float2(h3);
        ax = fmaf(v0, g0.x, ax); ay = fmaf(v0, g0.y, ay);
        ax = fmaf(v1, g1.x, ax); ay = fmaf(v1, g1.y, ay);
        ax = fmaf(v2, g2.x, ax); ay = fmaf(v2, g2.y, ay);
        ax = fmaf(v3, g3.x, ax); ay = fmaf(v3, g3.y, ay);
    }
    for (; e < p1; ++e) {
        int s = srcs[e]; float v = vals[e];
        float2 g = __half22float2(Xb[s * 32 + lane]);
        ax = fmaf(v, g.x, ax); ay = fmaf(v, g.y, ay);
    }
    size_t ro = boff2 + (size_t)n * 32 + lane;   // half2 index
    if (CHEB) {
        float2 mv = __half22float2(((const __half2*)XM)[ro]);
        ax = 2.f * ax - mv.x;
        ay = 2.f * ay - mv.y;
    }
    ((__half2*)T)[ro] = __floats2half2_rn(ax, ay);
}

// ---------------- tensor-core projection ----------------
// out[r, :] = bias + sum_m A_m[r, :] @ Wp_m ; 4 warps/block, 16 rows/warp
__global__ void __launch_bounds__(128) k_gemm_tc(
    const __half* __restrict__ Xh, const __half* __restrict__ T1,
    const __half* __restrict__ T2, const __half* __restrict__ T3,
    const __half* __restrict__ T4, const float* __restrict__ bias,
    float* __restrict__ out)
{
    __shared__ __half Wsh[MM * DD * DD];        // 40 KB, layout matches g_Wh
    __shared__ float  Bsh[16 * 64];             // bias broadcast tile
    int tid = threadIdx.x;
    int warp = tid >> 5;

    // cooperative loads
    const float4* ws = (const float4*)g_Wh;
    float4* wd = (float4*)Wsh;
#pragma unroll
    for (int i = tid; i < MM * DD * DD / 8; i += 128) wd[i] = ws[i];
#pragma unroll
    for (int i = tid; i < 16 * 64; i += 128) Bsh[i] = bias[i & 63];
    __syncthreads();

    size_t row0 = ((size_t)blockIdx.x * 4 + warp) * 16;

    wmma::fragment<wmma::accumulator, 16, 16, 16, float> c[4];
#pragma unroll
    for (int j = 0; j < 4; ++j)
        wmma::load_matrix_sync(c[j], &Bsh[j * 16], 64, wmma::mem_row_major);

    const __half* bufs[5] = {Xh, T1, T2, T3, T4};
#pragma unroll
    for (int m = 0; m < 5; ++m) {
        const __half* A = bufs[m] + row0 * DD;
#pragma unroll
        for (int kt = 0; kt < 4; ++kt) {
            wmma::fragment<wmma::matrix_a, 16, 16, 16, __half, wmma::row_major> a;
            wmma::load_matrix_sync(a, A + kt * 16, 64);
#pragma unroll
            for (int j = 0; j < 4; ++j) {
                wmma::fragment<wmma::matrix_b, 16, 16, 16, __half, wmma::row_major> b;
                wmma::load_matrix_sync(b, &Wsh[(m * 64 + kt * 16) * 64 + j * 16], 64);
                wmma::mma_sync(c[j], a, b, c[j]);
            }
        }
    }
#pragma unroll
    for (int j = 0; j < 4; ++j)
        wmma::store_matrix_sync(out + row0 * DD + j * 16, c[j], 64, wmma::mem_row_major);
}

// ---------------- launch ----------------
extern "C" void kernel_launch(void* const* d_in, const int* in_sizes, int n_in,
                              void* d_out, int out_size)
{
    const float* inputs  = (const float*)d_in[0];   // [B, N, D]
    const float* adj     = (const float*)d_in[1];   // [E]
    const int*   rows    = (const int*)d_in[2];     // [E]
    const int*   cols    = (const int*)d_in[3];     // [E]
    const float* weights = (const float*)d_in[4];   // [D*M, OUT]
    const float* biases  = (const float*)d_in[5];   // [1, OUT]
    float* out = (float*)d_out;                     // [B, N, OUT]
    (void)in_sizes; (void)n_in; (void)out_size;

    void *pP1, *pP2, *pS1, *pS2, *pV1, *pV2, *pX, *pT1, *pT2, *pT3, *pT4;
    cudaGetSymbolAddress(&pP1, g_ptr1);
    cudaGetSymbolAddress(&pP2, g_ptr2);
    cudaGetSymbolAddress(&pS1, g_src1);
    cudaGetSymbolAddress(&pS2, g_src2);
    cudaGetSymbolAddress(&pV1, g_val1);
    cudaGetSymbolAddress(&pV2, g_val2);
    cudaGetSymbolAddress(&pX,  g_Xh);
    cudaGetSymbolAddress(&pT1, g_T1);
    cudaGetSymbolAddress(&pT2, g_T2);
    cudaGetSymbolAddress(&pT3, g_T3);
    cudaGetSymbolAddress(&pT4, g_T4);

    k_zero<<<(NN + 255) / 256, 256>>>();
    k_degree<<<(EE + 255) / 256, 256>>>(rows, cols, adj);
    k_scan<<<1, 1024>>>();
    k_fill<<<(EE + 255) / 256, 256>>>(rows, cols, adj);

    k_cvt_x<<<(int)(((size_t)BB * NN * DD / 2 + 255) / 256), 256>>>(inputs);
    k_cvt_w<<<(MM * DD * DD + 255) / 256, 256>>>(weights);

    dim3 sg(NN / 8, BB);
    // T1 = S1 @ X0
    k_spmm<false><<<sg, 256>>>((const int*)pP1, (const int*)pS1, (const float*)pV1,
                               (const __half*)pX, nullptr, (__half*)pT1);
    // T2 = 2*S1 @ T1 - X0
    k_spmm<true><<<sg, 256>>>((const int*)pP1, (const int*)pS1, (const float*)pV1,
                              (const __half*)pT1, (const __half*)pX, (__half*)pT2);
    // T3 = S2 @ T1
    k_spmm<false><<<sg, 256>>>((const int*)pP2, (const int*)pS2, (const float*)pV2,
                               (const __half*)pT1, nullptr, (__half*)pT3);
    // T4 = 2*S2 @ T3 - T1
    k_spmm<true><<<sg, 256>>>((const int*)pP2, (const int*)pS2, (const float*)pV2,
                              (const __half*)pT3, (const __half*)pT1, (__half*)pT4);

    k_gemm_tc<<<(BB * NN) / 64, 128>>>((const __half*)pX, (const __half*)pT1,
                                       (const __half*)pT2, (const __half*)pT3,
                                       (const __half*)pT4, biases, out);
}

// round 3
// speedup vs baseline: 1.5262x; 1.4242x over previous
#include <cuda_runtime.h>
#include <cuda_fp16.h>
#include <mma.h>
#include <cstdint>

#define NN 16384
#define EE 524288
#define EPAD (EE + 4 * NN)
#define BB 32
#define DD 64
#define MM 5

using namespace nvcuda;

// ---------------- device scratch (static, allocation-free) ----------------
// fp16 operand buffers, TRANSPOSED layout: buf[(n*32 + b)*64 + d]
__device__ __half g_Xh[(size_t)BB * NN * DD];
__device__ __half g_T1[(size_t)BB * NN * DD];
__device__ __half g_T2[(size_t)BB * NN * DD];
__device__ __half g_T3[(size_t)BB * NN * DD];
__device__ __half g_T4[(size_t)BB * NN * DD];
__device__ __half g_Wh[MM * DD * DD];           // W permuted: [(m*64+k)*64+o]

__device__ float g_degr[NN];
__device__ float g_degc[NN];
__device__ int   g_cnt1[NN], g_cnt2[NN];
__device__ int   g_ptr1[NN + 1], g_ptr2[NN + 1];
__device__ int   g_cur1[NN], g_cur2[NN];
__device__ int   g_src1[EPAD], g_src2[EPAD];
__device__ float g_val1[EPAD], g_val2[EPAD];

// ---------------- init ----------------
__global__ void k_zero() {
    int i = blockIdx.x * blockDim.x + threadIdx.x;
    if (i < NN) {
        g_degr[i] = 0.f; g_degc[i] = 0.f;
        g_cnt1[i] = 0;   g_cnt2[i] = 0;
    }
}

__global__ void k_degree(const int* __restrict__ rows, const int* __restrict__ cols,
                         const float* __restrict__ adj) {
    int e = blockIdx.x * blockDim.x + threadIdx.x;
    if (e >= EE) return;
    int r = rows[e], c = cols[e];
    float a = adj[e];
    atomicAdd(&g_degr[r], a);
    atomicAdd(&g_degc[c], a);
    atomicAdd(&g_cnt1[c], 1);   // S1 scatters to cols
    atomicAdd(&g_cnt2[r], 1);   // S2 scatters to rows
}

// single-block exclusive scan; segments rounded up to multiple of 4, pads zeroed
__device__ void scan16k(const int* __restrict__ cnt, int* __restrict__ ptr,
                        int* __restrict__ cur, int* __restrict__ src,
                        float* __restrict__ val, int* sh) {
    int t = threadIdx.x;
    int base = t * 16;
    int loc[16], cr[16], cn[16];
    int s = 0;
#pragma unroll
    for (int j = 0; j < 16; ++j) {
        cn[j] = cnt[base + j];
        cr[j] = (cn[j] + 3) & ~3;       // padded segment length
        loc[j] = s; s += cr[j];
    }
    sh[t] = s;
    __syncthreads();
    for (int off = 1; off < 1024; off <<= 1) {
        int v = (t >= off) ? sh[t - off] : 0;
        __syncthreads();
        sh[t] += v;
        __syncthreads();
    }
    int pre = (t == 0) ? 0 : sh[t - 1];
#pragma unroll
    for (int j = 0; j < 16; ++j) {
        int p = pre + loc[j];
        ptr[base + j] = p;
        cur[base + j] = p;
        // zero the pad slots now (fill only writes [p, p+cnt))
        for (int q = p + cn[j]; q < p + cr[j]; ++q) { src[q] = 0; val[q] = 0.f; }
    }
    if (t == 1023) ptr[NN] = sh[1023];
    __syncthreads();
}

__global__ void k_scan() {
    __shared__ int sh[1024];
    scan16k(g_cnt1, g_ptr1, g_cur1, g_src1, g_val1, sh);
    scan16k(g_cnt2, g_ptr2, g_cur2, g_src2, g_val2, sh);
    int t = threadIdx.x;
    for (int i = t; i < NN; i += 1024) {
        float d = g_degr[i]; g_degr[i] = (d > 0.f) ? 1.f / d : 0.f;
        d = g_degc[i];       g_degc[i] = (d > 0.f) ? 1.f / d : 0.f;
    }
}

__global__ void k_fill(const int* __restrict__ rows, const int* __restrict__ cols,
                       const float* __restrict__ adj) {
    int e = blockIdx.x * blockDim.x + threadIdx.x;
    if (e >= EE) return;
    int r = rows[e], c = cols[e];
    float a = adj[e];
    int p = atomicAdd(&g_cur1[c], 1);
    g_src1[p] = r;
    g_val1[p] = a * g_degr[r];
    int q = atomicAdd(&g_cur2[r], 1);
    g_src2[q] = c;
    g_val2[q] = a * g_degc[c];
}

// ---------------- converts ----------------
// inputs [b][n][d] fp32 -> g_Xh [(n*32+b)*64+d] fp16 (transpose b<->n)
__global__ void k_cvt_x(const float* __restrict__ X) {
    int i = blockIdx.x * blockDim.x + threadIdx.x;     // half2 index in TARGET
    if (i >= BB * NN * (DD / 2)) return;
    int dh = i & 31;
    int b  = (i >> 5) & 31;
    int n  = i >> 10;
    float2 v = ((const float2*)X)[((size_t)b * NN + n) * 32 + dh];
    ((__half2*)g_Xh)[i] = __floats2half2_rn(v.x, v.y);
}

// permute W [(k*5+m)*64+o] -> g_Wh [(m*64+k)*64+o], fp16
__global__ void k_cvt_w(const float* __restrict__ W) {
    int idx = blockIdx.x * blockDim.x + threadIdx.x;
    if (idx >= MM * DD * DD) return;
    int m = idx / (DD * DD);
    int rem = idx - m * DD * DD;
    int k = rem >> 6, o = rem & 63;
    g_Wh[idx] = __float2half(W[(size_t)(k * MM + m) * DD + o]);
}

// ---------------- SpMM v3: warp = (dst node, 4 batches), LDG.128 gathers ----------------
__device__ __forceinline__ void acc8(float2* acc, uint4 g, float v) {
    __half2* h = (__half2*)&g;
#pragma unroll
    for (int k = 0; k < 4; ++k) {
        float2 f = __half22float2(h[k]);
        acc[k].x = fmaf(v, f.x, acc[k].x);
        acc[k].y = fmaf(v, f.y, acc[k].y);
    }
}

template <bool CHEB>
__global__ void __launch_bounds__(256) k_spmm(
    const int* __restrict__ ptr, const int* __restrict__ srcs,
    const float* __restrict__ vals, const __half* __restrict__ X,
    const __half* __restrict__ XM, __half* __restrict__ T)
{
    int lane = threadIdx.x & 31;
    int n = blockIdx.x * 8 + (threadIdx.x >> 5);
    int quad = blockIdx.y;                              // batches [quad*4, quad*4+4)
    // lane -> (batch-in-quad = lane>>3, 16B chunk = lane&7)
    int sub = (quad * 4 + (lane >> 3)) * 8 + (lane & 7); // uint4 index within 4KB node block
    const uint4* __restrict__ Xb = (const uint4*)X;

    int p0 = ptr[n], p1 = ptr[n + 1];                   // segment length multiple of 4
    float2 acc[4] = {{0.f,0.f},{0.f,0.f},{0.f,0.f},{0.f,0.f}};

    for (int base = p0; base < p1; base += 32) {
        int idx = base + lane;
        int s = 0; float v = 0.f;
        if (idx < p1) { s = srcs[idx]; v = vals[idx]; }
        int cnt = min(32, p1 - base);                   // multiple of 4
        for (int j = 0; j < cnt; j += 4) {
            int s0 = __shfl_sync(0xffffffffu, s, j);
            int s1 = __shfl_sync(0xffffffffu, s, j + 1);
            int s2 = __shfl_sync(0xffffffffu, s, j + 2);
            int s3 = __shfl_sync(0xffffffffu, s, j + 3);
            float v0 = __shfl_sync(0xffffffffu, v, j);
            float v1 = __shfl_sync(0xffffffffu, v, j + 1);
            float v2 = __shfl_sync(0xffffffffu, v, j + 2);
            float v3 = __shfl_sync(0xffffffffu, v, j + 3);
            uint4 g0 = Xb[s0 * 256 + sub];
            uint4 g1 = Xb[s1 * 256 + sub];
            uint4 g2 = Xb[s2 * 256 + sub];
            uint4 g3 = Xb[s3 * 256 + sub];
            acc8(acc, g0, v0);
            acc8(acc, g1, v1);
            acc8(acc, g2, v2);
            acc8(acc, g3, v3);
        }
    }

    size_t o = (size_t)n * 256 + sub;                   // uint4 units
    if (CHEB) {
        uint4 mg = ((const uint4*)XM)[o];
        __half2* mh = (__half2*)&mg;
#pragma unroll
        for (int k = 0; k < 4; ++k) {
            float2 f = __half22float2(mh[k]);
            acc[k].x = 2.f * acc[k].x - f.x;
            acc[k].y = 2.f * acc[k].y - f.y;
        }
    }
    uint4 r;
    __half2* rh = (__half2*)&r;
#pragma unroll
    for (int k = 0; k < 4; ++k) rh[k] = __floats2half2_rn(acc[k].x, acc[k].y);
    ((uint4*)T)[o] = r;
}

// ---------------- tensor-core projection ----------------
// A rows are (n*32+b); 16-row tile = one n, b in [0,16) or [16,32).
// out[b][n][o]: store with ldm = NN*64.
__global__ void __launch_bounds__(128) k_gemm_tc(
    const __half* __restrict__ Xh, const __half* __restrict__ T1,
    const __half* __restrict__ T2, const __half* __restrict__ T3,
    const __half* __restrict__ T4, const float* __restrict__ bias,
    float* __restrict__ out)
{
    __shared__ __half Wsh[MM * DD * DD];        // 40 KB
    __shared__ float  Bsh[16 * 64];
    int tid = threadIdx.x;
    int warp = tid >> 5;

    const float4* ws = (const float4*)g_Wh;
    float4* wd = (float4*)Wsh;
#pragma unroll
    for (int i = tid; i < MM * DD * DD / 8; i += 128) wd[i] = ws[i];
#pragma unroll
    for (int i = tid; i < 16 * 64; i += 128) Bsh[i] = bias[i & 63];
    __syncthreads();

    int tile = blockIdx.x * 4 + warp;
    int r0 = tile * 16;                 // global A row
    int n  = r0 >> 5;
    int b0 = r0 & 31;                   // 0 or 16

    wmma::fragment<wmma::accumulator, 16, 16, 16, float> c[4];
#pragma unroll
    for (int j = 0; j < 4; ++j)
        wmma::load_matrix_sync(c[j], &Bsh[j * 16], 64, wmma::mem_row_major);

    const __half* bufs[5] = {Xh, T1, T2, T3, T4};
#pragma unroll
    for (int m = 0; m < 5; ++m) {
        const __half* A = bufs[m] + (size_t)r0 * DD;
#pragma unroll
        for (int kt = 0; kt < 4; ++kt) {
            wmma::fragment<wmma::matrix_a, 16, 16, 16, __half, wmma::row_major> a;
            wmma::load_matrix_sync(a, A + kt * 16, 64);
#pragma unroll
            for (int j = 0; j < 4; ++j) {
                wmma::fragment<wmma::matrix_b, 16, 16, 16, __half, wmma::row_major> b;
                wmma::load_matrix_sync(b, &Wsh[(m * 64 + kt * 16) * 64 + j * 16], 64);
                wmma::mma_sync(c[j], a, b, c[j]);
            }
        }
    }
    float* ob = out + ((size_t)b0 * NN + n) * DD;
#pragma unroll
    for (int j = 0; j < 4; ++j)
        wmma::store_matrix_sync(ob + j * 16, c[j], NN * DD, wmma::mem_row_major);
}

// ---------------- launch ----------------
extern "C" void kernel_launch(void* const* d_in, const int* in_sizes, int n_in,
                              void* d_out, int out_size)
{
    const float* inputs  = (const float*)d_in[0];   // [B, N, D]
    const float* adj     = (const float*)d_in[1];   // [E]
    const int*   rows    = (const int*)d_in[2];     // [E]
    const int*   cols    = (const int*)d_in[3];     // [E]
    const float* weights = (const float*)d_in[4];   // [D*M, OUT]
    const float* biases  = (const float*)d_in[5];   // [1, OUT]
    float* out = (float*)d_out;                     // [B, N, OUT]
    (void)in_sizes; (void)n_in; (void)out_size;

    void *pP1, *pP2, *pS1, *pS2, *pV1, *pV2, *pX, *pT1, *pT2, *pT3, *pT4;
    cudaGetSymbolAddress(&pP1, g_ptr1);
    cudaGetSymbolAddress(&pP2, g_ptr2);
    cudaGetSymbolAddress(&pS1, g_src1);
    cudaGetSymbolAddress(&pS2, g_src2);
    cudaGetSymbolAddress(&pV1, g_val1);
    cudaGetSymbolAddress(&pV2, g_val2);
    cudaGetSymbolAddress(&pX,  g_Xh);
    cudaGetSymbolAddress(&pT1, g_T1);
    cudaGetSymbolAddress(&pT2, g_T2);
    cudaGetSymbolAddress(&pT3, g_T3);
    cudaGetSymbolAddress(&pT4, g_T4);

    k_zero<<<(NN + 255) / 256, 256>>>();
    k_degree<<<(EE + 255) / 256, 256>>>(rows, cols, adj);
    k_scan<<<1, 1024>>>();
    k_fill<<<(EE + 255) / 256, 256>>>(rows, cols, adj);

    k_cvt_x<<<(BB * NN * (DD / 2) + 255) / 256, 256>>>(inputs);
    k_cvt_w<<<(MM * DD * DD + 255) / 256, 256>>>(weights);

    dim3 sg(NN / 8, 8);
    // T1 = S1 @ X0
    k_spmm<false><<<sg, 256>>>((const int*)pP1, (const int*)pS1, (const float*)pV1,
                               (const __half*)pX, nullptr, (__half*)pT1);
    // T2 = 2*S1 @ T1 - X0
    k_spmm<true><<<sg, 256>>>((const int*)pP1, (const int*)pS1, (const float*)pV1,
                              (const __half*)pT1, (const __half*)pX, (__half*)pT2);
    // T3 = S2 @ T1
    k_spmm<false><<<sg, 256>>>((const int*)pP2, (const int*)pS2, (const float*)pV2,
                               (const __half*)pT1, nullptr, (__half*)pT3);
    // T4 = 2*S2 @ T3 - T1
    k_spmm<true><<<sg, 256>>>((const int*)pP2, (const int*)pS2, (const float*)pV2,
                              (const __half*)pT3, (const __half*)pT1, (__half*)pT4);

    k_gemm_tc<<<(BB * NN) / 64, 128>>>((const __half*)pX, (const __half*)pT1,
                                       (const __half*)pT2, (const __half*)pT3,
                                       (const __half*)pT4, biases, out);
}